// round 15
// baseline (speedup 1.0000x reference)
#include <cuda_runtime.h>
#include <cuda_bf16.h>
#include <cstdint>

#define NN   50000
#define EE   1000000
#define BB   2048
#define RR   3
#define INP  256
#define HID  512
#define OUTC 256
#define BN_EPS 1e-5f
#define K3_1 (3*INP)    // 768
#define K3_2 (3*HID)    // 1536

// ---------------- device scratch ----------------
__device__ int   g_pos[NN];
__device__ int   g_appear[RR][BB];
__device__ float g_deg[RR][BB];
__device__ int   g_kept[RR];
__device__ int   g_ks[RR][EE];
__device__ int   g_kd[RR][EE];
__device__ __align__(16) __nv_bfloat16 g_B1[HID * K3_1];
__device__ __align__(16) __nv_bfloat16 g_B2[OUTC * K3_2];
__device__ __align__(16) float g_XW[RR * BB * HID];
__device__ __align__(16) float g_AGG[RR * BB * HID];   // scatter acc, then v
__device__ __align__(16) float g_HW[RR * BB * OUTC];
__device__ float g_sum[RR][HID];
__device__ float g_sumsq[RR][HID];

// ---------------- helpers ----------------
__device__ __forceinline__ uint32_t smem_u32(const void* p) {
    uint32_t a;
    asm("{ .reg .u64 t; cvta.to.shared.u64 t, %1; cvt.u32.u64 %0, t; }"
        : "=r"(a) : "l"(p));
    return a;
}
__device__ __forceinline__ void ldsm_x4(uint32_t& r0, uint32_t& r1,
                                        uint32_t& r2, uint32_t& r3, uint32_t a) {
    asm volatile("ldmatrix.sync.aligned.m8n8.x4.shared.b16 {%0,%1,%2,%3}, [%4];"
                 : "=r"(r0), "=r"(r1), "=r"(r2), "=r"(r3) : "r"(a));
}
__device__ __forceinline__ void mma16816(float* d, const uint32_t* a,
                                         const uint32_t* b) {
    asm volatile(
        "mma.sync.aligned.m16n8k16.row.col.f32.bf16.bf16.f32 "
        "{%0,%1,%2,%3}, {%4,%5,%6,%7}, {%8,%9}, {%0,%1,%2,%3};"
        : "+f"(d[0]), "+f"(d[1]), "+f"(d[2]), "+f"(d[3])
        : "r"(a[0]), "r"(a[1]), "r"(a[2]), "r"(a[3]), "r"(b[0]), "r"(b[1]));
}
__device__ __forceinline__ void split2(float x, __nv_bfloat16& hi, __nv_bfloat16& lo) {
    hi = __float2bfloat16(x);
    lo = __float2bfloat16(x - __bfloat162float(hi));
}
// pack two floats as bf16 pair; seg==1 -> low residuals, else high parts
__device__ __forceinline__ uint32_t splitpack(float a, float b, int seg) {
    __nv_bfloat16 ha = __float2bfloat16(a);
    __nv_bfloat16 hb = __float2bfloat16(b);
    if (seg == 1) {
        ha = __float2bfloat16(a - __bfloat162float(ha));
        hb = __float2bfloat16(b - __bfloat162float(hb));
    }
    __nv_bfloat162 p = __halves2bfloat162(ha, hb);
    return *(uint32_t*)&p;
}

// ---------------- fused prologue (no feature pass) ----------------
__global__ void k_pre(const float* __restrict__ W1, const float* __restrict__ W2,
                      const int* __restrict__ bn) {
    int idx = blockIdx.x * blockDim.x + threadIdx.x;   // grid: RR*BB*HID/4
    if (idx < RR * BB * HID / 4)
        ((float4*)g_AGG)[idx] = make_float4(0.f, 0.f, 0.f, 0.f);
    if (idx < NN) {
        int lo = 0, hi = BB - 1, res = -1;
        while (lo <= hi) {
            int mid = (lo + hi) >> 1;
            int v = bn[mid];
            if (v == idx) { res = mid; break; }
            if (v < idx) lo = mid + 1; else hi = mid - 1;
        }
        g_pos[idx] = res;
    }
    if (idx < RR * BB) ((int*)g_appear)[idx] = 0;
    if (idx < RR * HID) { ((float*)g_sum)[idx] = 0.f; ((float*)g_sumsq)[idx] = 0.f; }
    if (idx < RR) g_kept[idx] = 0;
    if (idx < HID * INP) {
        int n = idx >> 8, k = idx & (INP - 1);
        __nv_bfloat16 hi2, lo2; split2(W1[(size_t)k * HID + n], hi2, lo2);
        size_t base = (size_t)n * K3_1;
        g_B1[base + k] = hi2;
        g_B1[base + INP + k] = hi2;
        g_B1[base + 2 * INP + k] = lo2;
    }
    if (idx < OUTC * HID) {
        int n = idx >> 9, k = idx & (HID - 1);
        __nv_bfloat16 hi2, lo2; split2(W2[(size_t)k * OUTC + n], hi2, lo2);
        size_t base = (size_t)n * K3_2;
        g_B2[base + k] = hi2;
        g_B2[base + HID + k] = hi2;
        g_B2[base + 2 * HID + k] = lo2;
    }
}

// ---------------- edge filtering (batched) ----------------
__global__ void k_scan(const int4* __restrict__ ei4) {
    const int r = blockIdx.y;
    const int4* src4 = ei4 + (size_t)r * 2 * (EE / 4);
    const int4* dst4 = src4 + EE / 4;
    int i = blockIdx.x * blockDim.x + threadIdx.x;
    if (i >= EE / 4) return;
    int4 s = src4[i], d = dst4[i];
    int ss[4] = {s.x, s.y, s.z, s.w};
    int dd[4] = {d.x, d.y, d.z, d.w};
#pragma unroll
    for (int j = 0; j < 4; j++) {
        int ps = g_pos[ss[j]];
        int pd = g_pos[dd[j]];
        if ((ps | pd) >= 0) {
            g_appear[r][ps] = 1;
            g_appear[r][pd] = 1;
            int ix = atomicAdd(&g_kept[r], 1);
            g_ks[r][ix] = ps;
            g_kd[r][ix] = pd;
        }
    }
}

// prefix scan + renumber + degree, one block per relation (1024 threads)
__global__ void __launch_bounds__(1024)
k_prefix_renum() {
    const int r = blockIdx.x;
    const int t = threadIdx.x;
    __shared__ int sc[1024];
    __shared__ int srank[BB];
    __shared__ float sdeg[BB];
    int a0 = g_appear[r][2 * t], a1 = g_appear[r][2 * t + 1];
    sc[t] = a0 + a1;
    sdeg[2 * t] = 0.f;
    sdeg[2 * t + 1] = 0.f;
    __syncthreads();
    for (int off = 1; off < 1024; off <<= 1) {
        int x = (t >= off) ? sc[t - off] : 0;
        __syncthreads();
        sc[t] += x;
        __syncthreads();
    }
    int pre = (t > 0) ? sc[t - 1] : 0;
    srank[2 * t] = pre + a0 - 1;
    srank[2 * t + 1] = pre + a0 + a1 - 1;
    __syncthreads();
    int ne = g_kept[r];
    for (int e = t; e < ne; e += 1024) {
        int rs = srank[g_ks[r][e]];
        int rd = srank[g_kd[r][e]];
        g_ks[r][e] = rs;
        g_kd[r][e] = rd;
        atomicAdd(&sdeg[rd], 1.0f);
    }
    __syncthreads();
    g_deg[r][2 * t] = 1.0f + sdeg[2 * t];
    g_deg[r][2 * t + 1] = 1.0f + sdeg[2 * t + 1];
}

// ---------------- GEMM1: on-the-fly split of feat rows --------------------
// CTA tile 128x128, 8 warps (4M x 2N), K=64 chunks, static smem (R12 core).
__global__ void __launch_bounds__(256)
k_mma1(const float* __restrict__ feat, const int* __restrict__ bn) {
    __shared__ alignas(1024) __nv_bfloat16 sA[128 * 64];
    __shared__ alignas(1024) __nv_bfloat16 sB[128 * 64];
    __shared__ int sbn[128];

    const int tid = threadIdx.x, wid = tid >> 5, lid = tid & 31;
    const int mwarp = wid & 3, nwarp = wid >> 2;
    const int rel = blockIdx.z;
    const int m0 = blockIdx.y * 128, n0 = blockIdx.x * 128;
    const float* featr = feat + (size_t)rel * NN * INP;
    const uint32_t sA0 = smem_u32(sA), sB0 = smem_u32(sB);

    if (tid < 128) sbn[tid] = bn[m0 + tid];
    __syncthreads();

    float acc[2][8][4];
#pragma unroll
    for (int mi = 0; mi < 2; mi++)
#pragma unroll
        for (int nf = 0; nf < 8; nf++)
#pragma unroll
            for (int j = 0; j < 4; j++) acc[mi][nf][j] = 0.0f;

    const int a_row = lid & 15, a_kb = (lid >> 4) * 16;
    const int b_nn = ((lid >> 4) << 3) + (lid & 7), b_kb = ((lid >> 3) & 1) * 16;

    for (int ch = 0; ch < K3_1 / 64; ch++) {
        const int seg = ch >> 2;            // 0:hi 1:lo 2:hi
        const int fcb = (ch & 3) * 64;      // feat col base
        const int kc = ch * 64;
#pragma unroll
        for (int it = 0; it < 4; it++) {
            int idx = it * 256 + tid;
            int r = idx >> 3, c16 = idx & 7;
            uint32_t byte = (uint32_t)(r * 128 + c16 * 16);
            uint32_t sw = byte ^ ((byte >> 3) & 0x70);
            const float* fp = featr + (size_t)sbn[r] * INP + fcb + c16 * 8;
            float4 f0 = *(const float4*)fp;
            float4 f1 = *(const float4*)(fp + 4);
            uint4 v;
            v.x = splitpack(f0.x, f0.y, seg);
            v.y = splitpack(f0.z, f0.w, seg);
            v.z = splitpack(f1.x, f1.y, seg);
            v.w = splitpack(f1.z, f1.w, seg);
            *(uint4*)((char*)sA + sw) = v;
            *(uint4*)((char*)sB + sw) =
                *(const uint4*)(g_B1 + (size_t)(n0 + r) * K3_1 + kc + c16 * 8);
        }
        __syncthreads();
#pragma unroll
        for (int ks = 0; ks < 4; ks++) {
            const int kbyte = ks * 32;
            uint32_t af[2][4];
#pragma unroll
            for (int mi = 0; mi < 2; mi++) {
                int row = mwarp * 32 + mi * 16 + a_row;
                uint32_t byte = (uint32_t)(row * 128 + kbyte + a_kb);
                uint32_t sw = byte ^ ((byte >> 3) & 0x70);
                ldsm_x4(af[mi][0], af[mi][1], af[mi][2], af[mi][3], sA0 + sw);
            }
            uint32_t bf_[8][2];
#pragma unroll
            for (int np = 0; np < 4; np++) {
                int nn = nwarp * 64 + np * 16 + b_nn;
                uint32_t byte = (uint32_t)(nn * 128 + kbyte + b_kb);
                uint32_t sw = byte ^ ((byte >> 3) & 0x70);
                uint32_t r0, r1, r2, r3;
                ldsm_x4(r0, r1, r2, r3, sB0 + sw);
                bf_[2 * np][0] = r0; bf_[2 * np][1] = r1;
                bf_[2 * np + 1][0] = r2; bf_[2 * np + 1][1] = r3;
            }
#pragma unroll
            for (int mi = 0; mi < 2; mi++)
#pragma unroll
                for (int nf = 0; nf < 8; nf++)
                    mma16816(acc[mi][nf], af[mi], bf_[nf]);
        }
        __syncthreads();
    }

    const int gid = lid >> 2, tg = lid & 3;
#pragma unroll
    for (int mi = 0; mi < 2; mi++) {
        const int rA = m0 + mwarp * 32 + mi * 16 + gid;
        const int rB = rA + 8;
#pragma unroll
        for (int nf = 0; nf < 8; nf++) {
            const int c = n0 + nwarp * 64 + nf * 8 + tg * 2;
            *(float2*)(g_XW + ((size_t)rel * BB + rA) * HID + c) =
                make_float2(acc[mi][nf][0], acc[mi][nf][1]);
            *(float2*)(g_XW + ((size_t)rel * BB + rB) * HID + c) =
                make_float2(acc[mi][nf][2], acc[mi][nf][3]);
        }
    }
}

// ---------------- GEMM2: on-the-fly BN + split of v (g_AGG) ---------------
// CTA tile 128x64, 8 warps (4M x 2N), K=64 chunks. BN sc/sh cached in smem.
__global__ void __launch_bounds__(256)
k_mma2(float* __restrict__ outp, const float* __restrict__ b2,
       const float* __restrict__ gamma, const float* __restrict__ beta) {
    __shared__ alignas(1024) __nv_bfloat16 sA[128 * 64];
    __shared__ alignas(1024) __nv_bfloat16 sB[64 * 64];
    __shared__ float ssc[HID];
    __shared__ float ssh[HID];

    const int tid = threadIdx.x, wid = tid >> 5, lid = tid & 31;
    const int mwarp = wid & 3, nwarp = wid >> 2;
    const int rel = blockIdx.z;
    const int m0 = blockIdx.y * 128, n0 = blockIdx.x * 64;
    const float* vsrc = g_AGG + (size_t)rel * BB * HID;
    const uint32_t sA0 = smem_u32(sA), sB0 = smem_u32(sB);

    const float invB = 1.0f / (float)BB;
    for (int c = tid; c < HID; c += 256) {
        float mu = g_sum[rel][c] * invB;
        float var = g_sumsq[rel][c] * invB - mu * mu;
        float sc = rsqrtf(var + BN_EPS) * gamma[c];
        ssc[c] = sc;
        ssh[c] = beta[c] - mu * sc;
    }
    __syncthreads();

    float acc[2][4][4];
#pragma unroll
    for (int mi = 0; mi < 2; mi++)
#pragma unroll
        for (int nf = 0; nf < 4; nf++)
#pragma unroll
            for (int j = 0; j < 4; j++) acc[mi][nf][j] = 0.0f;

    const int a_row = lid & 15, a_kb = (lid >> 4) * 16;
    const int b_nn = ((lid >> 4) << 3) + (lid & 7), b_kb = ((lid >> 3) & 1) * 16;

    for (int ch = 0; ch < K3_2 / 64; ch++) {
        const int seg = ch >> 3;            // 0:hi 1:lo 2:hi
        const int kpb = (ch & 7) * 64;      // v col base
        const int kc = ch * 64;
#pragma unroll
        for (int it = 0; it < 4; it++) {
            int idx = it * 256 + tid;
            int r = idx >> 3, c16 = idx & 7;
            uint32_t byte = (uint32_t)(r * 128 + c16 * 16);
            uint32_t sw = byte ^ ((byte >> 3) & 0x70);
            const int cb = kpb + c16 * 8;
            const float* vp = vsrc + (size_t)(m0 + r) * HID + cb;
            float4 f0 = *(const float4*)vp;
            float4 f1 = *(const float4*)(vp + 4);
            float h0 = f0.x * ssc[cb + 0] + ssh[cb + 0];
            float h1 = f0.y * ssc[cb + 1] + ssh[cb + 1];
            float h2 = f0.z * ssc[cb + 2] + ssh[cb + 2];
            float h3 = f0.w * ssc[cb + 3] + ssh[cb + 3];
            float h4 = f1.x * ssc[cb + 4] + ssh[cb + 4];
            float h5 = f1.y * ssc[cb + 5] + ssh[cb + 5];
            float h6 = f1.z * ssc[cb + 6] + ssh[cb + 6];
            float h7 = f1.w * ssc[cb + 7] + ssh[cb + 7];
            uint4 v;
            v.x = splitpack(h0, h1, seg);
            v.y = splitpack(h2, h3, seg);
            v.z = splitpack(h4, h5, seg);
            v.w = splitpack(h6, h7, seg);
            *(uint4*)((char*)sA + sw) = v;
            if (idx < 512)
                *(uint4*)((char*)sB + sw) =
                    *(const uint4*)(g_B2 + (size_t)(n0 + r) * K3_2 + kc + c16 * 8);
        }
        __syncthreads();
#pragma unroll
        for (int ks = 0; ks < 4; ks++) {
            const int kbyte = ks * 32;
            uint32_t af[2][4];
#pragma unroll
            for (int mi = 0; mi < 2; mi++) {
                int row = mwarp * 32 + mi * 16 + a_row;
                uint32_t byte = (uint32_t)(row * 128 + kbyte + a_kb);
                uint32_t sw = byte ^ ((byte >> 3) & 0x70);
                ldsm_x4(af[mi][0], af[mi][1], af[mi][2], af[mi][3], sA0 + sw);
            }
            uint32_t bf_[4][2];
#pragma unroll
            for (int np = 0; np < 2; np++) {
                int nn = nwarp * 32 + np * 16 + b_nn;
                uint32_t byte = (uint32_t)(nn * 128 + kbyte + b_kb);
                uint32_t sw = byte ^ ((byte >> 3) & 0x70);
                uint32_t r0, r1, r2, r3;
                ldsm_x4(r0, r1, r2, r3, sB0 + sw);
                bf_[2 * np][0] = r0; bf_[2 * np][1] = r1;
                bf_[2 * np + 1][0] = r2; bf_[2 * np + 1][1] = r3;
            }
#pragma unroll
            for (int mi = 0; mi < 2; mi++)
#pragma unroll
                for (int nf = 0; nf < 4; nf++)
                    mma16816(acc[mi][nf], af[mi], bf_[nf]);
        }
        __syncthreads();
    }

    const int gid = lid >> 2, tg = lid & 3;
#pragma unroll
    for (int mi = 0; mi < 2; mi++) {
        const int rA = m0 + mwarp * 32 + mi * 16 + gid;
        const int rB = rA + 8;
        const float d2A = 1.0f / g_deg[rel][rA];
        const float d2B = 1.0f / g_deg[rel][rB];
#pragma unroll
        for (int nf = 0; nf < 4; nf++) {
            const int c = n0 + nwarp * 32 + nf * 8 + tg * 2;
            float2 vA = make_float2(acc[mi][nf][0], acc[mi][nf][1]);
            float2 vB = make_float2(acc[mi][nf][2], acc[mi][nf][3]);
            size_t offA = ((size_t)rel * BB + rA) * OUTC + c;
            size_t offB = ((size_t)rel * BB + rB) * OUTC + c;
            *(float2*)(g_HW + offA) = vA;
            *(float2*)(g_HW + offB) = vB;
            float2 bb = *(const float2*)(b2 + c);
            *(float2*)(outp + offA) =
                make_float2(d2A * vA.x + bb.x, d2A * vA.y + bb.y);
            *(float2*)(outp + offB) =
                make_float2(d2B * vB.x + bb.x, d2B * vB.y + bb.y);
        }
    }
}

// ---------------- edge scatter ----------------
__global__ void k_agg_edges_h() {
    const int r = blockIdx.y;
    int ne = g_kept[r];
    const float* S = g_XW + (size_t)r * BB * HID;
    float* D = g_AGG + (size_t)r * BB * HID;
    for (int e = blockIdx.x; e < ne; e += gridDim.x) {
        int s = g_ks[r][e], d = g_kd[r][e];
        float coeff = rsqrtf(g_deg[r][s] * g_deg[r][d]);
        const float* sp = S + (size_t)s * HID;
        float* dp = D + (size_t)d * HID;
        for (int c = threadIdx.x; c < HID; c += blockDim.x)
            atomicAdd(&dp[c], coeff * sp[c]);
    }
}
__global__ void k_agg_edges_o(float* __restrict__ outp) {
    const int r = blockIdx.y;
    int ne = g_kept[r];
    const float* S = g_HW + (size_t)r * BB * OUTC;
    float* D = outp + (size_t)r * BB * OUTC;
    for (int e = blockIdx.x; e < ne; e += gridDim.x) {
        int s = g_ks[r][e], d = g_kd[r][e];
        float coeff = rsqrtf(g_deg[r][s] * g_deg[r][d]);
        const float* sp = S + (size_t)s * OUTC;
        float* dp = D + (size_t)d * OUTC;
        for (int c = threadIdx.x; c < OUTC; c += blockDim.x)
            atomicAdd(&dp[c], coeff * sp[c]);
    }
}

// ---------------- BN stats: v = AGG + XW/deg, write v back, accumulate ----
__global__ void k_bn_stats() {
    const int r = blockIdx.y;
    int c = threadIdx.x;  // 512
    int r0 = blockIdx.x * 32;
    float* agg = g_AGG + (size_t)r * BB * HID;
    const float* xw = g_XW + (size_t)r * BB * HID;
    float s = 0.0f, s2 = 0.0f;
#pragma unroll 4
    for (int i = 0; i < 32; i++) {
        float inv = 1.0f / g_deg[r][r0 + i];
        size_t off = (size_t)(r0 + i) * HID + c;
        float v = agg[off] + inv * xw[off];
        agg[off] = v;
        s += v;
        s2 += v * v;
    }
    atomicAdd(&g_sum[r][c], s);
    atomicAdd(&g_sumsq[r][c], s2);
}

// ---------------- host launch ----------------
extern "C" void kernel_launch(void* const* d_in, const int* in_sizes, int n_in,
                              void* d_out, int out_size) {
    const float* feat = (const float*)d_in[0];
    const float* W1 = (const float*)d_in[1];
    // b1 cancels in BatchNorm
    const float* W2 = (const float*)d_in[3];
    const float* b2 = (const float*)d_in[4];
    const float* gamma = (const float*)d_in[5];
    const float* beta = (const float*)d_in[6];
    const int* ei = (const int*)d_in[7];
    const int* bn = (const int*)d_in[8];
    float* out = (float*)d_out;

    static cudaStream_t s_side = nullptr;
    static cudaEvent_t ev_fork = nullptr, ev_join = nullptr;
    if (!s_side) {
        cudaStreamCreateWithFlags(&s_side, cudaStreamNonBlocking);
        cudaEventCreateWithFlags(&ev_fork, cudaEventDisableTiming);
        cudaEventCreateWithFlags(&ev_join, cudaEventDisableTiming);
    }

    k_pre<<<RR * BB * HID / 4 / 256, 256>>>(W1, W2, bn);

    // fork: edge path on side stream
    cudaEventRecord(ev_fork, 0);
    cudaStreamWaitEvent(s_side, ev_fork, 0);
    { dim3 g((EE / 4 + 255) / 256, RR); k_scan<<<g, 256, 0, s_side>>>((const int4*)ei); }
    k_prefix_renum<<<RR, 1024, 0, s_side>>>();
    cudaEventRecord(ev_join, s_side);

    // compute path on main stream
    { dim3 g(HID / 128, BB / 128, RR); k_mma1<<<g, 256>>>(feat, bn); }

    // join
    cudaStreamWaitEvent(0, ev_join, 0);

    { dim3 g(512, RR); k_agg_edges_h<<<g, 128>>>(); }
    { dim3 g(BB / 32, RR); k_bn_stats<<<g, 512>>>(); }
    { dim3 g(OUTC / 64, BB / 128, RR); k_mma2<<<g, 256>>>(out, b2, gamma, beta); }
    { dim3 g(512, RR); k_agg_edges_o<<<g, 128>>>(out); }
}